// round 4
// baseline (speedup 1.0000x reference)
#include <cuda_runtime.h>
#include <math.h>

#define D_MODEL     1024
#define SEQ_LEN     32768
#define NCHUNK      128
#define L_PER_CHUNK 256                 // SEQ_LEN / NCHUNK
#define NBLOCKS     512                 // NCHUNK * 4 d-quadrants; <= 148 SMs * occ 4
#define NTHREADS    256

typedef unsigned long long ull;

// Scratch + sync state (device globals; no allocation in kernel_launch)
__device__ float g_partial[NCHUNK * D_MODEL];         // [chunk][d]
__device__ __align__(16) float g_signal[D_MODEL];
__device__ unsigned g_ctr0 = 0, g_ctr1 = 0, g_ctr2 = 0;

// ---------------- packed f32x2 helpers (FFMA2 path, PTX-only) ---------------
__device__ __forceinline__ ull fma2(ull a, ull b, ull c) {
    ull d; asm("fma.rn.f32x2 %0,%1,%2,%3;" : "=l"(d) : "l"(a), "l"(b), "l"(c)); return d;
}
__device__ __forceinline__ ull add2(ull a, ull b) {
    ull d; asm("add.rn.f32x2 %0,%1,%2;" : "=l"(d) : "l"(a), "l"(b)); return d;
}
__device__ __forceinline__ ull mul2(ull a, ull b) {
    ull d; asm("mul.rn.f32x2 %0,%1,%2;" : "=l"(d) : "l"(a), "l"(b)); return d;
}
__device__ __forceinline__ ull dup2(float x) {
    unsigned u = __float_as_uint(x); return ((ull)u << 32) | (ull)u;
}
__device__ __forceinline__ float2 unpk(ull v) {
    float2 r; asm("mov.b64 {%0,%1},%2;" : "=f"(r.x), "=f"(r.y) : "l"(v)); return r;
}

// Packed sin-polynomial (2 terms at once): reduce by 2pi via magic rounding,
// deg-13 odd Taylor on [-pi,pi]. 12 packed FMA-pipe ops per pair.
__device__ __forceinline__ ull polyacc(ull ph, ull acc,
                                       ull kI2P, ull kMG, ull kNMG, ull kN2P,
                                       ull kC13, ull kC11, ull kC9, ull kC7,
                                       ull kC5, ull kC3, ull kONE) {
    ull y = fma2(ph, kI2P, kMG);       // phi/2pi + magic  (RNE round)
    ull k = add2(y, kNMG);             // k = round(phi/2pi)
    ull r = fma2(k, kN2P, ph);         // r = phi - k*2pi, |r| <= pi
    ull s = mul2(r, r);
    ull h = fma2(kC13, s, kC11);
    h     = fma2(h, s, kC9);
    h     = fma2(h, s, kC7);
    h     = fma2(h, s, kC5);
    h     = fma2(h, s, kC3);
    ull u = fma2(s, h, kONE);          // 1 + s*h(s)
    return fma2(r, u, acc);            // acc += r*(1+s*h)
}

// Deterministic grid sync: int-counter barrier, co-resident grid required.
#define GRID_SYNC(CTR)                                                   \
    do {                                                                 \
        __syncthreads();                                                 \
        if (threadIdx.x == 0) {                                          \
            __threadfence();                                             \
            atomicAdd(&(CTR), 1u);                                       \
            while (*(volatile unsigned*)&(CTR) < NBLOCKS) __nanosleep(64); \
        }                                                                \
        __syncthreads();                                                 \
    } while (0)

// ---------------------------------------------------------------------------
// One fused kernel: phase A (sin partials, MUFU/packed-poly hybrid) ->
// grid sync -> phase B (chunk reduction) -> grid sync -> phase C (GEMV).
// ---------------------------------------------------------------------------
__global__ void __launch_bounds__(NTHREADS, 4)
fused_kernel(const float* __restrict__ inputs, const float* __restrict__ W,
             const float* __restrict__ bias, float* __restrict__ out) {
    __shared__ __align__(16) float fA[L_PER_CHUNK];   // 2pi*x[l]
    __shared__ __align__(16) float fB[L_PER_CHUNK];   // (2pi*x[l]) * log1p(l)
    __shared__ float sred[16];

    const int tid   = threadIdx.x;
    const int bid   = blockIdx.x;
    const int chunk = bid >> 2;          // 0..127
    const int dquad = bid & 3;
    const int d     = dquad * 256 + tid;

    // ---- phase A setup: per-l coefficients into shared -----------------
    {
        const int l = chunk * L_PER_CHUNK + tid;
        float a = 6.283185307179586f * inputs[l];
        fA[tid] = a;
        fB[tid] = a * log1pf((float)l);
    }
    __syncthreads();

    // packed constants
    const ull kI2P = dup2(0.15915494309189535f);
    const ull kMG  = dup2(12582912.0f);              // 1.5 * 2^23
    const ull kNMG = dup2(-12582912.0f);
    const ull kN2P = dup2(-6.28318548202514648f);    // -fl32(2pi)
    const ull kC13 = dup2(1.6059044e-10f);
    const ull kC11 = dup2(-2.5052108e-8f);
    const ull kC9  = dup2(2.7557319e-6f);
    const ull kC7  = dup2(-1.9841270e-4f);
    const ull kC5  = dup2(8.3333333e-3f);
    const ull kC3  = dup2(-1.6666667e-1f);
    const ull kONE = dup2(1.0f);

    const ull t2 = dup2((float)d * (1.0f / 1023.0f));

    const ulonglong2* A2 = (const ulonglong2*)fA;    // 64 entries (4 terms each)
    const ulonglong2* B2 = (const ulonglong2*)fB;

    float a0 = 0.f, a1 = 0.f, a2 = 0.f, a3 = 0.f;    // MUFU accumulators
    ull P0 = 0ull, P1 = 0ull;                        // packed poly accumulators

    // 16 groups x 16 terms: 12 via MUFU.SIN, 4 via packed polynomial.
#pragma unroll 2
    for (int g = 0; g < 16; ++g) {
        ulonglong2 Aa = A2[g * 4 + 0], Ab = A2[g * 4 + 1];
        ulonglong2 Ac = A2[g * 4 + 2], Ad = A2[g * 4 + 3];
        ulonglong2 Ba = B2[g * 4 + 0], Bb = B2[g * 4 + 1];
        ulonglong2 Bc = B2[g * 4 + 2], Bd = B2[g * 4 + 3];

        ull p; float2 u;
        p = fma2(Aa.x, t2, Ba.x); u = unpk(p); a0 += __sinf(u.x); a1 += __sinf(u.y);
        p = fma2(Aa.y, t2, Ba.y); u = unpk(p); a2 += __sinf(u.x); a3 += __sinf(u.y);
        p = fma2(Ab.x, t2, Bb.x); u = unpk(p); a0 += __sinf(u.x); a1 += __sinf(u.y);
        p = fma2(Ab.y, t2, Bb.y); u = unpk(p); a2 += __sinf(u.x); a3 += __sinf(u.y);
        p = fma2(Ac.x, t2, Bc.x); u = unpk(p); a0 += __sinf(u.x); a1 += __sinf(u.y);
        p = fma2(Ac.y, t2, Bc.y); u = unpk(p); a2 += __sinf(u.x); a3 += __sinf(u.y);

        p  = fma2(Ad.x, t2, Bd.x);
        P0 = polyacc(p, P0, kI2P, kMG, kNMG, kN2P, kC13, kC11, kC9, kC7, kC5, kC3, kONE);
        p  = fma2(Ad.y, t2, Bd.y);
        P1 = polyacc(p, P1, kI2P, kMG, kNMG, kN2P, kC13, kC11, kC9, kC7, kC5, kC3, kONE);
    }

    {
        float2 q0 = unpk(P0), q1 = unpk(P1);
        float total = ((a0 + a1) + (a2 + a3)) + ((q0.x + q0.y) + (q1.x + q1.y));
        g_partial[chunk * D_MODEL + d] = total;
    }

    GRID_SYNC(g_ctr0);

    // ---- phase B: reduce 128 chunks; block handles d = 2*bid + (tid>>7) ---
    {
        const int dd = (bid << 1) | (tid >> 7);
        const int c  = tid & 127;
        float v = g_partial[c * D_MODEL + dd];
#pragma unroll
        for (int off = 16; off > 0; off >>= 1)
            v += __shfl_down_sync(0xffffffffu, v, off);
        if ((tid & 31) == 0) sred[tid >> 5] = v;   // 8 warps
        __syncthreads();
        if (tid < 2) {
            float s = (sred[tid * 4 + 0] + sred[tid * 4 + 1]) +
                      (sred[tid * 4 + 2] + sred[tid * 4 + 3]);
            g_signal[(bid << 1) + tid] = s;
        }
    }

    GRID_SYNC(g_ctr1);

    // ---- phase C: GEMV out = signal @ W^T + b; block does rows bid, bid+512
    for (int rr = 0; rr < 2; ++rr) {
        const int row = bid + rr * 512;
        float4 w  = ((const float4*)(W + row * D_MODEL))[tid];
        float4 sg = ((const float4*)g_signal)[tid];
        float acc = w.x * sg.x;
        acc = fmaf(w.y, sg.y, acc);
        acc = fmaf(w.z, sg.z, acc);
        acc = fmaf(w.w, sg.w, acc);
#pragma unroll
        for (int off = 16; off > 0; off >>= 1)
            acc += __shfl_down_sync(0xffffffffu, acc, off);
        if ((tid & 31) == 0) sred[tid >> 5] = acc;
        __syncthreads();
        if (tid == 0) {
            float s = ((sred[0] + sred[1]) + (sred[2] + sred[3])) +
                      ((sred[4] + sred[5]) + (sred[6] + sred[7]));
            out[row] = s + bias[row];
        }
        __syncthreads();
    }

    // ---- counter cleanup so graph replays start from zero ----------------
    if (tid == 0) {
        __threadfence();
        unsigned old = atomicAdd(&g_ctr2, 1u);
        if (old == NBLOCKS - 1) {
            g_ctr0 = 0; g_ctr1 = 0; g_ctr2 = 0;
            __threadfence();
        }
    }
}

// ---------------------------------------------------------------------------
extern "C" void kernel_launch(void* const* d_in, const int* in_sizes, int n_in,
                              void* d_out, int out_size) {
    const float* inputs = (const float*)d_in[0];   // [32768]
    const float* W      = (const float*)d_in[1];   // [1024,1024]
    const float* b      = (const float*)d_in[2];   // [1024]
    float*       out    = (float*)d_out;           // [1024]

    fused_kernel<<<NBLOCKS, NTHREADS>>>(inputs, W, b, out);
    (void)in_sizes; (void)n_in; (void)out_size;
}

// round 5
// speedup vs baseline: 1.3068x; 1.3068x over previous
#include <cuda_runtime.h>
#include <math.h>

#define D_MODEL   1024
#define SEQ_LEN   32768
#define NBLK_A    512                   // phase-A blocks
#define LPB       64                    // l's per block (512*64 = 32768)
#define LPW       8                     // l's per warp

#define TWO_PI    6.283185307179586f
#define INV_2PI   0.15915494309189535f
#define MAGIC     12582912.0f           // 1.5 * 2^23
#define C1_2PI    6.28318548202514648f  // fl32(2*pi)

// Scratch (device globals; no allocation in kernel_launch)
__device__ float g_partial[NBLK_A * D_MODEL];   // [block][d], 2MB
__device__ __align__(16) float g_signal[D_MODEL];

// ---------------------------------------------------------------------------
// Kernel A: signal partial sums via Chebyshev recurrence over d.
// Block: 8 warps; each warp covers ALL 1024 d (lane k owns d=32k..32k+31)
// for LPW l's. Per (l, 32d): 2 seed sins (MUFU, after exact 2pi reduction)
// + 30 recurrence FFMAs + 32 accumulate FADDs -> ~2.2 FMA-pipe ops/term.
// ---------------------------------------------------------------------------
__global__ void __launch_bounds__(256, 4)
sinsum_kernel(const float* __restrict__ inputs) {
    __shared__ float4 co[LPB];            // (a, b=a*log1p(l), c=2cos(a/1023), 0)
    __shared__ float  sred[8 * 1056];     // 8 warps x (33*32) transpose buffer

    const int tid = threadIdx.x;
    const int w   = tid >> 5;
    const int k   = tid & 31;

    if (tid < LPB) {
        const int l = blockIdx.x * LPB + tid;
        float x  = inputs[l];
        float a  = TWO_PI * x;
        float p  = log1pf((float)l);
        float dl = a * (1.0f / 1023.0f);          // per-d phase step
        float d2 = dl * dl;
        // c = 2*cos(dl), |dl| <= ~0.03: 2 - d2 + d2^2/12 (error << ulp)
        float c  = fmaf(d2 * d2, (1.0f / 12.0f), 2.0f - d2);
        co[tid]  = make_float4(a, a * p, c, 0.0f);
    }
    __syncthreads();

    const float tk0 = (float)(k * 32)     * (1.0f / 1023.0f);
    const float tk1 = (float)(k * 32 + 1) * (1.0f / 1023.0f);

    float acc[32];
#pragma unroll
    for (int n = 0; n < 32; ++n) acc[n] = 0.0f;

#pragma unroll 4
    for (int j = 0; j < LPW; ++j) {
        float4 C = co[w * LPW + j];       // LDS.128 broadcast

        // seeds at d = 32k and 32k+1, range-reduced then MUFU sin
        float phi0 = fmaf(C.x, tk0, C.y);
        float y0   = fmaf(phi0, INV_2PI, MAGIC);
        float q0   = y0 - MAGIC;
        float r0   = fmaf(q0, -C1_2PI, phi0);
        float s0   = __sinf(r0);

        float phi1 = fmaf(C.x, tk1, C.y);
        float y1   = fmaf(phi1, INV_2PI, MAGIC);
        float q1   = y1 - MAGIC;
        float r1   = fmaf(q1, -C1_2PI, phi1);
        float s1   = __sinf(r1);

        acc[0] += s0;
        acc[1] += s1;

#pragma unroll
        for (int n = 2; n < 32; ++n) {
            float s2 = fmaf(C.z, s1, -s0);   // sin(phi + n*delta)
            acc[n] += s2;
            s0 = s1; s1 = s2;
        }
    }

    // Transpose via smem: sred[w][33*n + k] (conflict-free STS per n)
#pragma unroll
    for (int n = 0; n < 32; ++n)
        sred[w * 1056 + 33 * n + k] = acc[n];
    __syncthreads();

    // Block-reduce over 8 warps; thread handles 4 consecutive d
    const int d0 = tid * 4;
    float o0 = 0.f, o1 = 0.f, o2 = 0.f, o3 = 0.f;
#pragma unroll
    for (int ww = 0; ww < 8; ++ww) {
        const float* sb = &sred[ww * 1056];
        o0 += sb[33 * ((d0 + 0) & 31) + ((d0 + 0) >> 5)];
        o1 += sb[33 * ((d0 + 1) & 31) + ((d0 + 1) >> 5)];
        o2 += sb[33 * ((d0 + 2) & 31) + ((d0 + 2) >> 5)];
        o3 += sb[33 * ((d0 + 3) & 31) + ((d0 + 3) >> 5)];
    }
    ((float4*)(g_partial + blockIdx.x * D_MODEL))[tid] =
        make_float4(o0, o1, o2, o3);
}

// ---------------------------------------------------------------------------
// Kernel B: reduce 512 slices -> signal. grid 128 x 256.
// Block b: d-range [8b, 8b+8); thread (sp=tid>>3, di=tid&7) sums 16 slices.
// ---------------------------------------------------------------------------
__global__ void reduce_kernel() {
    __shared__ float sb[32][8];
    const int b   = blockIdx.x;
    const int tid = threadIdx.x;
    const int sp  = tid >> 3;
    const int di  = tid & 7;
    const int d   = b * 8 + di;

    float s = 0.0f;
#pragma unroll
    for (int j = 0; j < 16; ++j)
        s += g_partial[(sp + 32 * j) * D_MODEL + d];
    sb[sp][di] = s;
    __syncthreads();

    if (tid < 8) {
        float t = 0.0f;
#pragma unroll
        for (int i = 0; i < 32; ++i) t += sb[i][tid];
        g_signal[b * 8 + tid] = t;
    }
}

// ---------------------------------------------------------------------------
// Kernel C: GEMV out = signal @ W^T + b. grid 256 x 128, warp per row.
// ---------------------------------------------------------------------------
__global__ void gemv_kernel(const float* __restrict__ W,
                            const float* __restrict__ bias,
                            float* __restrict__ out) {
    __shared__ __align__(16) float ssig[D_MODEL];

    const int tid = threadIdx.x;
#pragma unroll
    for (int i = tid; i < D_MODEL / 4; i += 128)
        ((float4*)ssig)[i] = ((const float4*)g_signal)[i];
    __syncthreads();

    const int warp = tid >> 5;
    const int lane = tid & 31;
    const int row  = blockIdx.x * 4 + warp;

    const float4* w4 = (const float4*)(W + row * D_MODEL);
    float acc = 0.0f;
#pragma unroll
    for (int kk = lane; kk < D_MODEL / 4; kk += 32) {
        float4 wv = w4[kk];
        float4 sv = ((const float4*)ssig)[kk];
        acc = fmaf(wv.x, sv.x, acc);
        acc = fmaf(wv.y, sv.y, acc);
        acc = fmaf(wv.z, sv.z, acc);
        acc = fmaf(wv.w, sv.w, acc);
    }
#pragma unroll
    for (int off = 16; off > 0; off >>= 1)
        acc += __shfl_down_sync(0xffffffffu, acc, off);

    if (lane == 0) out[row] = acc + bias[row];
}

// ---------------------------------------------------------------------------
extern "C" void kernel_launch(void* const* d_in, const int* in_sizes, int n_in,
                              void* d_out, int out_size) {
    const float* inputs = (const float*)d_in[0];   // [32768]
    const float* W      = (const float*)d_in[1];   // [1024,1024]
    const float* b      = (const float*)d_in[2];   // [1024]
    float*       out    = (float*)d_out;           // [1024]

    sinsum_kernel<<<NBLK_A, 256>>>(inputs);
    reduce_kernel<<<D_MODEL / 8, 256>>>();
    gemv_kernel<<<D_MODEL / 4, 128>>>(W, b, out);
    (void)in_sizes; (void)n_in; (void)out_size;
}